// round 14
// baseline (speedup 1.0000x reference)
#include <cuda_runtime.h>

// RayTracing, SINGLE fused kernel, block-local compaction, QUADRATIC sdf,
// TWO RAYS PER THREAD in the trace phase (ILP for the serial sqrt/fma chain).
//  Phase 1: 128 threads trace 256 rays/block -> outputs + smask queue.
//  Phase 2: sqrt-free 100-step scan at 4 threads/ray (quad shuffle reduce,
//           exact first-occurrence tie-break). Non-sec rays finalize with z_o;
//           sec rays push bracket to queue2.
//  Phase 3: secant at 1 thread/ray over queue2.
//
// Output layout (float32): [curr_pts (N*3)][net_mask (N)][acc_s (N)], N = out_size/5.
// object_mask arrives as int32.

namespace rt {

constexpr int   ST_ITERS   = 10;
constexpr float SDF_THRESH = 5e-5f;
constexpr int   NSTEPS     = 100;
constexpr int   NSECANT    = 8;
constexpr float INV99      = 1.0f / 99.0f;
constexpr float R2THRESH   = 0.25f;    // SDF_RADIUS^2
constexpr int   LPR        = 4;        // lanes per ray in scan
constexpr int   KPL        = 25;       // 100/4, exact
constexpr int   BLK        = 128;      // threads per block
constexpr int   RPB        = 256;      // rays per block (2 per thread)

__device__ __forceinline__ float fsqrt_fast(float x) {
    float y;
    asm("sqrt.approx.f32 %0, %1;" : "=f"(y) : "f"(x));
    return y;
}

// q(t) = a*t^2 + b*t + qc  (qc = |o|^2 + 1e-12)
__device__ __forceinline__ float q_quad(float qa, float qb, float qc, float t) {
    return fmaf(t, fmaf(t, qa, qb), qc);
}

// sdf along ray = sqrt(q(t)) - 0.5
__device__ __forceinline__ float s_quad(float qa, float qb, float qc, float t) {
    return fsqrt_fast(q_quad(qa, qb, qc, t)) - 0.5f;
}

__global__ void __launch_bounds__(BLK, 8)
fused_kernel(const float* __restrict__ cam,
             const float* __restrict__ dirs,
             const int* __restrict__ objm,
             float* __restrict__ out, int n)
{
    const unsigned FULL = 0xffffffffu;
    __shared__ int   s_cnt, s2_cnt;
    __shared__ int   s_rid[RPB];
    __shared__ float s_lo[RPB], s_hi[RPB];
    __shared__ int   s2_rid[RPB];
    __shared__ float s2_zl[RPB], s2_zh[RPB];

    int tid = threadIdx.x;
    if (tid == 0) { s_cnt = 0; s2_cnt = 0; }
    __syncthreads();

    // ================= Phase 1: trace (2 rays per thread) =================
    int   idx[2];
    bool  valid[2];
    float ox[2], oy[2], oz[2], dx[2], dy[2], dz[2];
    float a[2], b[2], qc[2];
    float accs[2], acce[2], ns[2], ne[2];
    bool  us[2], ue[2];

#pragma unroll
    for (int r = 0; r < 2; ++r) {
        int i = blockIdx.x * RPB + r * BLK + tid;
        idx[r] = i;
        valid[r] = i < n;
        int j = valid[r] ? i : 0;

        ox[r] = cam[3 * j + 0]; oy[r] = cam[3 * j + 1]; oz[r] = cam[3 * j + 2];
        dx[r] = dirs[3 * j + 0]; dy[r] = dirs[3 * j + 1]; dz[r] = dirs[3 * j + 2];

        a[r]  = fmaf(dx[r], dx[r], fmaf(dy[r], dy[r], dz[r] * dz[r]));
        b[r]  = 2.0f * fmaf(ox[r], dx[r], fmaf(oy[r], dy[r], oz[r] * dz[r]));
        float c = fmaf(ox[r], ox[r], fmaf(oy[r], oy[r], oz[r] * oz[r])) - 1.0f;
        qc[r] = fmaf(ox[r], ox[r], fmaf(oy[r], oy[r], fmaf(oz[r], oz[r], 1e-12f)));

        float under = fmaf(b[r], b[r], -4.0f * a[r] * c);
        bool  mask = under > 0.0f;
        float sq = fsqrt_fast(fmaxf(under, 0.0f));
        float nearv = mask ? (-sq - b[r]) * 0.5f : 0.0f;
        float farv  = mask ? ( sq - b[r]) * 0.5f : 0.0f;
        nearv = fmaxf(nearv, 0.01f);
        farv  = fmaxf(farv, 0.01f);

        us[r] = mask; ue[r] = mask;
        accs[r] = nearv; acce[r] = farv;
        ns[r] = s_quad(a[r], b[r], qc[r], accs[r]);
        ne[r] = s_quad(a[r], b[r], qc[r], acce[r]);
    }

#pragma unroll
    for (int it = 0; it < ST_ITERS; ++it) {
#pragma unroll
        for (int r = 0; r < 2; ++r) {
            // merged _upd_mask
            bool usn = us[r] && (ns[r] > SDF_THRESH);
            float cs = usn ? ns[r] : 0.0f;
            us[r] = usn;
            bool uen = ue[r] && (ne[r] > SDF_THRESH);
            float ce = uen ? ne[r] : 0.0f;
            ue[r] = uen;

            accs[r] += cs;
            acce[r] -= ce;
            ns[r] = s_quad(a[r], b[r], qc[r], accs[r]);
            ne[r] = s_quad(a[r], b[r], qc[r], acce[r]);

            // line search: LINE_STEP_ITERS = 1, step = 0.5
            bool nps = us[r] && (ns[r] < 0.0f);
            bool npe = ue[r] && (ne[r] < 0.0f);
            {
                float accs2 = fmaf(-0.5f, cs, accs[r]);
                float s2 = s_quad(a[r], b[r], qc[r], accs2);
                if (nps) { accs[r] = accs2; ns[r] = s2; }
            }
            {
                float acce2 = fmaf(0.5f, ce, acce[r]);
                float s2 = s_quad(a[r], b[r], qc[r], acce2);
                if (npe) { acce[r] = acce2; ne[r] = s2; }
            }
            bool ok = accs[r] < acce[r];
            us[r] = us[r] && ok;
            ue[r] = ue[r] && ok;
        }
    }

#pragma unroll
    for (int r = 0; r < 2; ++r) {
        // final _upd_mask on start side
        us[r] = us[r] && (ns[r] > SDF_THRESH);

        bool netm  = accs[r] < acce[r];
        bool smask = us[r] && valid[r];
        int i = idx[r];

        if (valid[r]) {
            out[3 * i + 0] = fmaf(accs[r], dx[r], ox[r]);
            out[3 * i + 1] = fmaf(accs[r], dy[r], oy[r]);
            out[3 * i + 2] = fmaf(accs[r], dz[r], oz[r]);
            out[3 * n + i] = netm ? 1.0f : 0.0f;
            out[4 * n + i] = accs[r];
        }

        if (smask) {
            int q = atomicAdd(&s_cnt, 1);
            s_rid[q] = i;
            s_lo[q]  = accs[r];
            s_hi[q]  = acce[r];
        }
    }
    __syncthreads();

    // ================= Phase 2: scan (4 threads/ray) =================
    int cnt = s_cnt;
    int sub = tid & (LPR - 1);          // lane in quad

    for (int base = 0; base < cnt; base += BLK / LPR) {
        int rslot = base + (tid >> 2);
        bool active = rslot < cnt;
        int q = active ? rslot : 0;

        int rid = s_rid[q];
        float smin = s_lo[q];
        float smax = s_hi[q];
        float range = smax - smin;

        float rox = cam[3 * rid + 0], roy = cam[3 * rid + 1], roz = cam[3 * rid + 2];
        float rdx = dirs[3 * rid + 0], rdy = dirs[3 * rid + 1], rdz = dirs[3 * rid + 2];
        bool obj = objm[rid] != 0;

        float a2 = fmaf(rdx, rdx, fmaf(rdy, rdy, rdz * rdz));
        float b2 = 2.0f * fmaf(rox, rdx, fmaf(roy, rdy, roz * rdz));
        float c2 = fmaf(rox, rox, fmaf(roy, roy, fmaf(roz, roz, 1e-12f)));

        int   kbase = sub * KPL;
        int   ind_neg = NSTEPS, oidx = NSTEPS - 1;
        float best_q = 1e30f;
        float fk = (float)kbase;         // exact; +1.0f stays exact (k < 2^24)
#pragma unroll 5
        for (int kk = 0; kk < KPL; ++kk) {
            int k = kbase + kk;
            float t  = fk * INV99;       // bit-identical to (float)k * INV99
            float z  = fmaf(t, range, smin);
            float qv = q_quad(a2, b2, c2, z);
            ind_neg  = min(ind_neg, (qv < R2THRESH) ? k : NSTEPS);
            if (qv < best_q) { best_q = qv; oidx = k; }
            fk += 1.0f;
        }

        // quad reduction (xor 1,2 stays inside the quad)
#pragma unroll
        for (int m = 1; m < LPR; m <<= 1) {
            int   in2 = __shfl_xor_sync(FULL, ind_neg, m);
            float bq2 = __shfl_xor_sync(FULL, best_q, m);
            int   oi2 = __shfl_xor_sync(FULL, oidx, m);
            ind_neg = min(ind_neg, in2);
            if (bq2 < best_q || (bq2 == best_q && oi2 < oidx)) {
                best_q = bq2; oidx = oi2;
            }
        }

        bool net_surface = (ind_neg < NSTEPS);
        int  ind = net_surface ? ind_neg : (NSTEPS - 1);
        bool sec = net_surface && obj;   // complement of p_out over queued rays

        if (active && sub == 0) {
            out[3 * n + rid] = net_surface ? 1.0f : 0.0f;
            if (!sec) {
                float z_o = fmaf((float)oidx * INV99, range, smin);
                out[3 * rid + 0] = fmaf(z_o, rdx, rox);
                out[3 * rid + 1] = fmaf(z_o, rdy, roy);
                out[3 * rid + 2] = fmaf(z_o, rdz, roz);
                out[4 * n + rid] = z_o;
            } else {
                int   ilow  = (ind > 0) ? (ind - 1) : 0;
                float z_ind = fmaf((float)ind * INV99, range, smin);
                float z_l   = fmaf((float)ilow * INV99, range, smin);
                int q2 = atomicAdd(&s2_cnt, 1);
                s2_rid[q2] = rid;
                s2_zl[q2]  = z_l;
                s2_zh[q2]  = z_ind;
            }
        }
    }
    __syncthreads();

    // ================= Phase 3: secant (1 thread/ray) =================
    int cnt2 = s2_cnt;
    for (int q = tid; q < cnt2; q += BLK) {
        int   rid = s2_rid[q];
        float zl  = s2_zl[q];
        float zh  = s2_zh[q];

        float rox = cam[3 * rid + 0], roy = cam[3 * rid + 1], roz = cam[3 * rid + 2];
        float rdx = dirs[3 * rid + 0], rdy = dirs[3 * rid + 1], rdz = dirs[3 * rid + 2];

        float a2 = fmaf(rdx, rdx, fmaf(rdy, rdy, rdz * rdz));
        float b2 = 2.0f * fmaf(rox, rdx, fmaf(roy, rdy, roz * rdz));
        float c2 = fmaf(rox, rox, fmaf(roy, roy, fmaf(roz, roz, 1e-12f)));

        float sl = fsqrt_fast(q_quad(a2, b2, c2, zl)) - 0.5f;
        float sh = fsqrt_fast(q_quad(a2, b2, c2, zh)) - 0.5f;

        float den = sh - sl;
        den = (den == 0.0f) ? 1.0f : den;
        float z = zl - sl * __fdividef(zh - zl, den);
#pragma unroll
        for (int k = 0; k < NSECANT; ++k) {
            float s = fsqrt_fast(q_quad(a2, b2, c2, z)) - 0.5f;
            if (s > 0.0f) { zl = z; sl = s; }
            if (s < 0.0f) { zh = z; sh = s; }
            den = sh - sl;
            den = (den == 0.0f) ? 1.0f : den;
            z = zl - sl * __fdividef(zh - zl, den);
        }

        out[3 * rid + 0] = fmaf(z, rdx, rox);
        out[3 * rid + 1] = fmaf(z, rdy, roy);
        out[3 * rid + 2] = fmaf(z, rdz, roz);
        out[4 * n + rid] = z;
        // net_mask for sec rays already written in phase 2
    }
}

} // namespace rt

extern "C" void kernel_launch(void* const* d_in, const int* in_sizes, int n_in,
                              void* d_out, int out_size)
{
    const float* cam  = (const float*)d_in[0];
    const float* dirs = (const float*)d_in[1];
    const int*   objm = (const int*)d_in[2];
    float* out = (float*)d_out;

    int n = out_size / 5;
    int blocks = (n + rt::RPB - 1) / rt::RPB;
    rt::fused_kernel<<<blocks, rt::BLK>>>(cam, dirs, objm, out, n);
}